// round 8
// baseline (speedup 1.0000x reference)
#include <cuda_runtime.h>
#include <cuda_fp16.h>
#include <cstdint>

// Problem constants (fixed by the dataset)
#define BB 32      // batch
#define II 2048    // input capsules
#define CC 16      // input atoms (contraction dim)
#define DD 32      // output capsules
#define AA 16      // output atoms
#define OO 512     // DD*AA
#define BO (BB*OO) // 16384
#define NBMAX 160
#define NT 1024

typedef unsigned long long ull;

// Scratch (static __device__ arrays: no dynamic allocation)
__device__ __half g_votes[(size_t)II * BB * OO];     // [i][b][o] fp16, 67 MB (kept L2-resident)
__device__ float  g_part[(size_t)NBMAX * BO];        // per-block partials, 10.5 MB
__device__ float  g_actS[BO];                        // act0, then act0+act1
__device__ unsigned g_count;                          // barrier arrive counter (self-resetting)
__device__ volatile unsigned g_sense;                 // barrier generation (monotonic)

// ---------------- packed f32x2 helpers ----------------
__device__ __forceinline__ ull pack2(float lo, float hi) {
    ull r; asm("mov.b64 %0, {%1,%2};" : "=l"(r) : "f"(lo), "f"(hi)); return r;
}
__device__ __forceinline__ void unpack2(ull v, float& lo, float& hi) {
    asm("mov.b64 {%0,%1}, %2;" : "=f"(lo), "=f"(hi) : "l"(v));
}
__device__ __forceinline__ void fma2(ull& d, ull a, ull b) {
    asm("fma.rn.f32x2 %0, %1, %2, %0;" : "+l"(d) : "l"(a), "l"(b));
}
__device__ __forceinline__ void add2(ull& d, ull a) {
    asm("add.rn.f32x2 %0, %1, %0;" : "+l"(d) : "l"(a));
}

#define WBUF_F4 2048                       // float4s per W buffer (32 KB)
#define SMEM_TOTAL (2*32768 + 2*2048)      // 2 W buffers + 2 x buffers = 69632 B

// ---------------------------------------------------------------------------
// Software grid barrier (sense-reversing). nb blocks co-resident (1/SM).
// ---------------------------------------------------------------------------
__device__ __forceinline__ void grid_sync(int nb) {
    __syncthreads();
    if (threadIdx.x == 0) {
        unsigned gen = g_sense;
        __threadfence();
        if (atomicAdd(&g_count, 1u) == (unsigned)(nb - 1)) {
            g_count = 0;
            __threadfence();
            g_sense = gen + 1;
        } else {
            while (g_sense == gen) __nanosleep(32);
        }
        __threadfence();
    }
    __syncthreads();
}

// ---------------------------------------------------------------------------
// Squash phase: blocks 0..127 active; block -> (b = bx>>2, oq4 = bx&3).
// 1024 threads = 32 float4-cols x 32 k-slices; smem tree; lane groups of 4
// = one 16-atom capsule. Fixed order -> deterministic.
// ---------------------------------------------------------------------------
__device__ __forceinline__ void squash_phase(char* smem, int nb, float scale,
                                             const float* __restrict__ bias,
                                             float* __restrict__ dst, int accumulate) {
    if (blockIdx.x < 128) {
        float4* red = (float4*)smem;                 // [32][33] float4 (17 KB)
        const int b    = blockIdx.x >> 2;
        const int oq4  = blockIdx.x & 3;
        const int col  = threadIdx.x & 31;
        const int ks   = threadIdx.x >> 5;
        const int gcol = b * 128 + oq4 * 32 + col;   // global float4 column
        const float4* gp = (const float4*)g_part;

        float4 s = make_float4(0.f, 0.f, 0.f, 0.f);
        for (int k = ks; k < nb; k += 32) {
            float4 v = gp[(size_t)k * (BO / 4) + gcol];
            s.x += v.x; s.y += v.y; s.z += v.z; s.w += v.w;
        }
        red[ks * 33 + col] = s;
        __syncthreads();

        if (threadIdx.x < 32) {
            float4 sum = red[col];
#pragma unroll
            for (int j = 1; j < 32; j++) {
                float4 v = red[j * 33 + col];
                sum.x += v.x; sum.y += v.y; sum.z += v.z; sum.w += v.w;
            }
            const float4 bi = ((const float4*)bias)[oq4 * 32 + col];
            float4 val;
            val.x = fmaf(sum.x, scale, bi.x);
            val.y = fmaf(sum.y, scale, bi.y);
            val.z = fmaf(sum.z, scale, bi.z);
            val.w = fmaf(sum.w, scale, bi.w);

            float n2 = (val.x * val.x + val.y * val.y) + (val.z * val.z + val.w * val.w);
            n2 += __shfl_xor_sync(0xffffffffu, n2, 1);
            n2 += __shfl_xor_sync(0xffffffffu, n2, 2);
            const float f = sqrtf(n2) / (1.f + n2);

            float4* dp = (float4*)dst + gcol;
            if (accumulate) {
                float4 cur = *dp;
                cur.x = fmaf(val.x, f, cur.x); cur.y = fmaf(val.y, f, cur.y);
                cur.z = fmaf(val.z, f, cur.z); cur.w = fmaf(val.w, f, cur.w);
                *dp = cur;
            } else {
                *dp = make_float4(val.x * f, val.y * f, val.z * f, val.w * f);
            }
        }
    }
    __syncthreads();
}

// ---------------------------------------------------------------------------
// Route phase: block bx owns i in [ilo, ihi); warp = one b; lane = one d.
// STREAM=1 (pass 2): __ldcs streaming loads (votes dead afterwards).
// STREAM=0 (pass 1): default allocate (keep for pass 2). Prefetch next i
// before the softmax chain; dot and accumulate in f32x2.
// ---------------------------------------------------------------------------
template <int STREAM>
__device__ __forceinline__ void route_phase(int nb) {
    const int b    = threadIdx.x >> 5;
    const int lane = threadIdx.x & 31;
    const int bx   = blockIdx.x;
    const int ilo  = (bx * II) / nb;
    const int ihi  = ((bx + 1) * II) / nb;
    const int d    = lane;

    ull arp[8];
    {
        const float4* ap = (const float4*)(g_actS + (b * DD + d) * AA);
        float4 a0 = ap[0], a1 = ap[1], a2 = ap[2], a3 = ap[3];
        arp[0] = pack2(a0.x, a0.y); arp[1] = pack2(a0.z, a0.w);
        arp[2] = pack2(a1.x, a1.y); arp[3] = pack2(a1.z, a1.w);
        arp[4] = pack2(a2.x, a2.y); arp[5] = pack2(a2.z, a2.w);
        arp[6] = pack2(a3.x, a3.y); arp[7] = pack2(a3.z, a3.w);
    }

    ull acc[8];
#pragma unroll
    for (int k = 0; k < 8; k++) acc[k] = 0ull;

    const uint4* vbase = (const uint4*)(g_votes + (size_t)b * OO + d * 16);
    const int stride = (BB * OO) / 8;                 // uint4 stride per i
    uint4 p0 = STREAM ? __ldcs(vbase + (size_t)ilo * stride)
                      : __ldg(vbase + (size_t)ilo * stride);
    uint4 p1 = STREAM ? __ldcs(vbase + (size_t)ilo * stride + 1)
                      : __ldg(vbase + (size_t)ilo * stride + 1);

    for (int i = ilo; i < ihi; i++) {
        uint4 c0 = p0, c1 = p1;
        if (i + 1 < ihi) {                    // prefetch next i before the chain
            const uint4* np = vbase + (size_t)(i + 1) * stride;
            p0 = STREAM ? __ldcs(np)     : __ldg(np);
            p1 = STREAM ? __ldcs(np + 1) : __ldg(np + 1);
        }

        ull vpk[8];
        {
            const __half2* h0 = (const __half2*)&c0;
            const __half2* h1 = (const __half2*)&c1;
#pragma unroll
            for (int j = 0; j < 4; j++) {
                float2 f = __half22float2(h0[j]); vpk[j]     = pack2(f.x, f.y);
                float2 g = __half22float2(h1[j]); vpk[4 + j] = pack2(g.x, g.y);
            }
        }

        ull u2 = 0ull;
#pragma unroll
        for (int k = 0; k < 8; k++) fma2(u2, vpk[k], arp[k]);
        float ulo, uhi; unpack2(u2, ulo, uhi);
        const float u = ulo + uhi;

        // softmax over d (32 lanes); |u| small enough to skip max-subtract
        float e = __expf(u);
        float s = e;
#pragma unroll
        for (int o = 16; o >= 1; o >>= 1) s += __shfl_xor_sync(0xffffffffu, s, o);
        const float r = __fdividef(e, s);
        const ull rr = pack2(r, r);
#pragma unroll
        for (int k = 0; k < 8; k++) fma2(acc[k], rr, vpk[k]);
    }

    float* dst = g_part + (size_t)bx * BO + (b * DD + d) * AA;
#pragma unroll
    for (int k = 0; k < 4; k++) {
        float l0, h0, l1, h1;
        unpack2(acc[2 * k], l0, h0);
        unpack2(acc[2 * k + 1], l1, h1);
        ((float4*)dst)[k] = make_float4(l0, h0, l1, h1);
    }
}

// ---------------------------------------------------------------------------
// Fused persistent kernel: votes -> squash0 -> route1 -> squash1 -> route2
// -> squash2, with software grid barriers between phases.
// ---------------------------------------------------------------------------
__global__ __launch_bounds__(NT, 1) void caps_kernel(const float* __restrict__ x,
                                                     const float* __restrict__ w,
                                                     const float* __restrict__ bias,
                                                     float* __restrict__ out,
                                                     int nb) {
    extern __shared__ __align__(16) char smem[];

    // ================= Phase 1: votes =================
    // 32 warps = 4 o-quarters x 8 b-groups(4 b); lane owns 4 consecutive o.
    // W tile: __ldcs (evict-first streaming -> W does NOT evict votes from L2)
    // into registers, then STS; double-buffered with ONE barrier per i
    // (STS(it+2) ordered after sync(it+1) which is after compute(it)).
    {
        float4* swbuf  = (float4*)smem;                  // [2][2048] float4
        float4* sxbuf4 = (float4*)(smem + 2 * 32768);    // [2][128] float4
        float*  sxbuf  = (float*)sxbuf4;

        const int t    = threadIdx.x;
        const int lane = t & 31;
        const int wid  = t >> 5;
        const int oq   = wid >> 3;       // o-quarter (0..3)
        const int bg   = wid & 7;        // b-group (4 b each)
        const int bx   = blockIdx.x;
        const int n    = (II - bx + nb - 1) / nb;
        const int qidx = oq * 32 + lane;            // float4 index within a c-row
        const int obase = oq * 128 + lane * 4;
        const int xb = t >> 2, xp = t & 3;          // x-staging role (t < 128)

        ull sacc[4][2];
#pragma unroll
        for (int j = 0; j < 4; j++) { sacc[j][0] = 0ull; sacc[j][1] = 0ull; }

        // prologue: stage W(bx), x(bx) into registers
        float4 wpf0, wpf1, xpf;
        {
            const float4* wsrc = (const float4*)(w + (size_t)bx * CC * OO);
            wpf0 = __ldcs(wsrc + t);
            wpf1 = __ldcs(wsrc + t + 1024);
            if (t < 128)
                xpf = __ldcs((const float4*)(x + ((size_t)xb * II + bx) * CC) + xp);
        }

        for (int it = 0; it < n; it++) {
            const int i = bx + it * nb;
            const bool hn = (it + 1) < n;
            const int buf = it & 1;

            // stage registers -> smem buffer `buf`
            swbuf[buf * WBUF_F4 + t]        = wpf0;
            swbuf[buf * WBUF_F4 + t + 1024] = wpf1;
            if (t < 128) sxbuf4[buf * 128 + t] = xpf;
            __syncthreads();

            // issue streaming loads for it+1 (overlap with compute below)
            if (hn) {
                const int i2 = i + nb;
                const float4* wsrc = (const float4*)(w + (size_t)i2 * CC * OO);
                wpf0 = __ldcs(wsrc + t);
                wpf1 = __ldcs(wsrc + t + 1024);
                if (t < 128)
                    xpf = __ldcs((const float4*)(x + ((size_t)xb * II + i2) * CC) + xp);
            }

            const float4* sw4 = swbuf + buf * WBUF_F4;
            const float*  sxp = sxbuf + buf * 512;

            ull acc[4][2];
#pragma unroll
            for (int j = 0; j < 4; j++) { acc[j][0] = 0ull; acc[j][1] = 0ull; }

#pragma unroll
            for (int c = 0; c < CC; c++) {
                const float4 wa = sw4[c * 128 + qidx];
                const ull wv0 = pack2(wa.x, wa.y);
                const ull wv1 = pack2(wa.z, wa.w);
#pragma unroll
                for (int bb = 0; bb < 4; bb++) {
                    const float xs = sxp[(bg * 4 + bb) * CC + c];   // warp-uniform broadcast
                    const ull xx = pack2(xs, xs);
                    fma2(acc[bb][0], xx, wv0);
                    fma2(acc[bb][1], xx, wv1);
                }
            }

            // store fp16 votes (256 B coalesced per warp per bb) + iter0 partials
#pragma unroll
            for (int bb = 0; bb < 4; bb++) {
                const int b = bg * 4 + bb;
                float l0, h0, l1, h1;
                unpack2(acc[bb][0], l0, h0);
                unpack2(acc[bb][1], l1, h1);
                __half2 hh[2] = { __floats2half2_rn(l0, h0), __floats2half2_rn(l1, h1) };
                *(uint2*)(g_votes + ((size_t)i * BB + b) * OO + obase) = *(uint2*)hh;
                add2(sacc[bb][0], acc[bb][0]);
                add2(sacc[bb][1], acc[bb][1]);
            }
        }

        // deterministic per-block partial write (row = blockIdx.x)
#pragma unroll
        for (int bb = 0; bb < 4; bb++) {
            const int b = bg * 4 + bb;
            float l0, h0, l1, h1;
            unpack2(sacc[bb][0], l0, h0);
            unpack2(sacc[bb][1], l1, h1);
            *(float4*)(g_part + (size_t)bx * BO + b * OO + obase) = make_float4(l0, h0, l1, h1);
        }
    }

    grid_sync(nb);
    squash_phase(smem, nb, 1.0f / 32.0f, bias, g_actS, 0);  // actS = act0
    grid_sync(nb);
    route_phase<0>(nb);                                     // softmax(u(act0)); keep votes in L2
    grid_sync(nb);
    squash_phase(smem, nb, 1.0f, bias, g_actS, 1);          // actS = act0 + act1
    grid_sync(nb);
    route_phase<1>(nb);                                     // softmax(u(act0+act1)); streaming reads
    grid_sync(nb);
    squash_phase(smem, nb, 1.0f, bias, out, 0);             // final activation
}

// ---------------------------------------------------------------------------
extern "C" void kernel_launch(void* const* d_in, const int* in_sizes, int n_in,
                              void* d_out, int out_size) {
    const float* x    = (const float*)d_in[0];
    const float* w    = (const float*)d_in[1];
    const float* bias = (const float*)d_in[2];
    float* out = (float*)d_out;

    int dev = 0, sm = 148;
    cudaGetDevice(&dev);
    cudaDeviceGetAttribute(&sm, cudaDevAttrMultiProcessorCount, dev);
    int nb = sm < NBMAX ? sm : NBMAX;
    if (nb < 128) nb = 128;  // squash uses 128 blocks; all real targets have >=128 SMs

    cudaFuncSetAttribute(caps_kernel, cudaFuncAttributeMaxDynamicSharedMemorySize, SMEM_TOTAL);
    caps_kernel<<<nb, NT, SMEM_TOTAL>>>(x, w, bias, out, nb);
}

// round 9
// speedup vs baseline: 1.1890x; 1.1890x over previous
#include <cuda_runtime.h>
#include <cuda_fp16.h>
#include <cstdint>

// Problem constants (fixed by the dataset)
#define BB 32      // batch
#define II 2048    // input capsules
#define CC 16      // input atoms (contraction dim)
#define DD 32      // output capsules
#define AA 16      // output atoms
#define OO 512     // DD*AA
#define BO (BB*OO) // 16384
#define NBMAX 160
#define NT 1024

typedef unsigned long long ull;

// Scratch (static __device__ arrays: no dynamic allocation)
__device__ __half g_votes[(size_t)II * BB * OO];     // [i][b][o] fp16, 67 MB
__device__ float  g_part[(size_t)NBMAX * BO];        // per-block partials, 10.5 MB
__device__ float  g_actS[BO];                        // act0, then act0+act1
__device__ unsigned g_count;                          // barrier arrive counter (self-resetting)
__device__ volatile unsigned g_sense;                 // barrier generation (monotonic)

// ---------------- packed f32x2 helpers ----------------
__device__ __forceinline__ ull pack2(float lo, float hi) {
    ull r; asm("mov.b64 %0, {%1,%2};" : "=l"(r) : "f"(lo), "f"(hi)); return r;
}
__device__ __forceinline__ void unpack2(ull v, float& lo, float& hi) {
    asm("mov.b64 {%0,%1}, %2;" : "=f"(lo), "=f"(hi) : "l"(v));
}
__device__ __forceinline__ void fma2(ull& d, ull a, ull b) {
    asm("fma.rn.f32x2 %0, %1, %2, %0;" : "+l"(d) : "l"(a), "l"(b));
}
__device__ __forceinline__ void add2(ull& d, ull a) {
    asm("add.rn.f32x2 %0, %1, %0;" : "+l"(d) : "l"(a));
}

// ---------------- cp.async helpers ----------------
__device__ __forceinline__ void cpa16(void* dst, const void* src) {
    unsigned sdst = (unsigned)__cvta_generic_to_shared(dst);
    asm volatile("cp.async.cg.shared.global [%0], [%1], 16;\n" :: "r"(sdst), "l"(src));
}
__device__ __forceinline__ void cpa4(void* dst, const void* src) {
    unsigned sdst = (unsigned)__cvta_generic_to_shared(dst);
    asm volatile("cp.async.ca.shared.global [%0], [%1], 4;\n" :: "r"(sdst), "l"(src));
}
#define CP_COMMIT() asm volatile("cp.async.commit_group;\n")
#define CP_WAIT(N)  asm volatile("cp.async.wait_group %0;\n" :: "n"(N))

#define WBUF_F4 2048                       // float4s per W buffer (32 KB)
#define XT_ROW  36                         // padded x-transpose row (floats), 16B-aligned
#define XT_BUF  (CC * XT_ROW)              // floats per x buffer (576)
#define SMEM_TOTAL (2*32768 + 2*XT_BUF*4 + 256)

// ---------------------------------------------------------------------------
// Software grid barrier (sense-reversing). nb blocks co-resident (1/SM).
// ---------------------------------------------------------------------------
__device__ __forceinline__ void grid_sync(int nb) {
    __syncthreads();
    if (threadIdx.x == 0) {
        unsigned gen = g_sense;
        __threadfence();
        if (atomicAdd(&g_count, 1u) == (unsigned)(nb - 1)) {
            g_count = 0;
            __threadfence();
            g_sense = gen + 1;
        } else {
            while (g_sense == gen) __nanosleep(32);
        }
        __threadfence();
    }
    __syncthreads();
}

// ---------------------------------------------------------------------------
// Squash phase: blocks 0..127 active; block -> (b = bx>>2, oq4 = bx&3).
// 1024 threads = 32 float4-cols x 32 k-slices; smem tree; lane groups of 4
// = one 16-atom capsule. Fixed order -> deterministic.
// ---------------------------------------------------------------------------
__device__ __forceinline__ void squash_phase(char* smem, int nb, float scale,
                                             const float* __restrict__ bias,
                                             float* __restrict__ dst, int accumulate) {
    if (blockIdx.x < 128) {
        float4* red = (float4*)smem;                 // [32][33] float4 (17 KB)
        const int b    = blockIdx.x >> 2;
        const int oq4  = blockIdx.x & 3;
        const int col  = threadIdx.x & 31;
        const int ks   = threadIdx.x >> 5;
        const int gcol = b * 128 + oq4 * 32 + col;   // global float4 column
        const float4* gp = (const float4*)g_part;

        float4 s = make_float4(0.f, 0.f, 0.f, 0.f);
        for (int k = ks; k < nb; k += 32) {
            float4 v = gp[(size_t)k * (BO / 4) + gcol];
            s.x += v.x; s.y += v.y; s.z += v.z; s.w += v.w;
        }
        red[ks * 33 + col] = s;
        __syncthreads();

        if (threadIdx.x < 32) {
            float4 sum = red[col];
#pragma unroll
            for (int j = 1; j < 32; j++) {
                float4 v = red[j * 33 + col];
                sum.x += v.x; sum.y += v.y; sum.z += v.z; sum.w += v.w;
            }
            const float4 bi = ((const float4*)bias)[oq4 * 32 + col];
            float4 val;
            val.x = fmaf(sum.x, scale, bi.x);
            val.y = fmaf(sum.y, scale, bi.y);
            val.z = fmaf(sum.z, scale, bi.z);
            val.w = fmaf(sum.w, scale, bi.w);

            float n2 = (val.x * val.x + val.y * val.y) + (val.z * val.z + val.w * val.w);
            n2 += __shfl_xor_sync(0xffffffffu, n2, 1);
            n2 += __shfl_xor_sync(0xffffffffu, n2, 2);
            const float f = sqrtf(n2) / (1.f + n2);

            float4* dp = (float4*)dst + gcol;
            if (accumulate) {
                float4 cur = *dp;
                cur.x = fmaf(val.x, f, cur.x); cur.y = fmaf(val.y, f, cur.y);
                cur.z = fmaf(val.z, f, cur.z); cur.w = fmaf(val.w, f, cur.w);
                *dp = cur;
            } else {
                *dp = make_float4(val.x * f, val.y * f, val.z * f, val.w * f);
            }
        }
    }
    __syncthreads();
}

// ---------------------------------------------------------------------------
// Route phase: block bx owns i in [ilo, ihi); warp = one b; lane = one d.
// STREAM=1 (pass 2): __ldcs streaming (votes dead after; keeps DRAM quiet).
// Prefetch next i before the softmax chain; dot and accumulate in f32x2.
// ---------------------------------------------------------------------------
template <int STREAM>
__device__ __forceinline__ void route_phase(int nb) {
    const int b    = threadIdx.x >> 5;
    const int lane = threadIdx.x & 31;
    const int bx   = blockIdx.x;
    const int ilo  = (bx * II) / nb;
    const int ihi  = ((bx + 1) * II) / nb;
    const int d    = lane;

    ull arp[8];
    {
        const float4* ap = (const float4*)(g_actS + (b * DD + d) * AA);
        float4 a0 = ap[0], a1 = ap[1], a2 = ap[2], a3 = ap[3];
        arp[0] = pack2(a0.x, a0.y); arp[1] = pack2(a0.z, a0.w);
        arp[2] = pack2(a1.x, a1.y); arp[3] = pack2(a1.z, a1.w);
        arp[4] = pack2(a2.x, a2.y); arp[5] = pack2(a2.z, a2.w);
        arp[6] = pack2(a3.x, a3.y); arp[7] = pack2(a3.z, a3.w);
    }

    ull acc[8];
#pragma unroll
    for (int k = 0; k < 8; k++) acc[k] = 0ull;

    const uint4* vbase = (const uint4*)(g_votes + (size_t)b * OO + d * 16);
    const int stride = (BB * OO) / 8;                 // uint4 stride per i
    uint4 p0 = STREAM ? __ldcs(vbase + (size_t)ilo * stride)
                      : __ldg(vbase + (size_t)ilo * stride);
    uint4 p1 = STREAM ? __ldcs(vbase + (size_t)ilo * stride + 1)
                      : __ldg(vbase + (size_t)ilo * stride + 1);

    for (int i = ilo; i < ihi; i++) {
        uint4 c0 = p0, c1 = p1;
        if (i + 1 < ihi) {                    // prefetch next i before the chain
            const uint4* np = vbase + (size_t)(i + 1) * stride;
            p0 = STREAM ? __ldcs(np)     : __ldg(np);
            p1 = STREAM ? __ldcs(np + 1) : __ldg(np + 1);
        }

        ull vpk[8];
        {
            const __half2* h0 = (const __half2*)&c0;
            const __half2* h1 = (const __half2*)&c1;
#pragma unroll
            for (int j = 0; j < 4; j++) {
                float2 f = __half22float2(h0[j]); vpk[j]     = pack2(f.x, f.y);
                float2 g = __half22float2(h1[j]); vpk[4 + j] = pack2(g.x, g.y);
            }
        }

        ull u2 = 0ull;
#pragma unroll
        for (int k = 0; k < 8; k++) fma2(u2, vpk[k], arp[k]);
        float ulo, uhi; unpack2(u2, ulo, uhi);
        const float u = ulo + uhi;

        // softmax over d (32 lanes); |u| small enough to skip max-subtract
        float e = __expf(u);
        float s = e;
#pragma unroll
        for (int o = 16; o >= 1; o >>= 1) s += __shfl_xor_sync(0xffffffffu, s, o);
        const float r = __fdividef(e, s);
        const ull rr = pack2(r, r);
#pragma unroll
        for (int k = 0; k < 8; k++) fma2(acc[k], rr, vpk[k]);
    }

    float* dst = g_part + (size_t)bx * BO + (b * DD + d) * AA;
#pragma unroll
    for (int k = 0; k < 4; k++) {
        float l0, h0, l1, h1;
        unpack2(acc[2 * k], l0, h0);
        unpack2(acc[2 * k + 1], l1, h1);
        ((float4*)dst)[k] = make_float4(l0, h0, l1, h1);
    }
}

// ---------------------------------------------------------------------------
// Fused persistent kernel: votes -> squash0 -> route1 -> squash1 -> route2
// -> squash2, with software grid barriers between phases.
// ---------------------------------------------------------------------------
__global__ __launch_bounds__(NT, 1) void caps_kernel(const float* __restrict__ x,
                                                     const float* __restrict__ w,
                                                     const float* __restrict__ bias,
                                                     float* __restrict__ out,
                                                     int nb) {
    extern __shared__ __align__(16) char smem[];

    // ================= Phase 1: votes =================
    // 32 warps = 4 o-quarters x 8 b-groups(4 b); lane owns 4 consecutive o.
    // W: cp.async double-buffered, 1 LDS.128 per c (conflict-free).
    // x: transposed smem tile [c][XT_ROW] loaded via 4-byte cp.async in the
    //    same pipeline -> 1 broadcast LDS.128 per c (1 crossbar cyc) instead
    //    of 4 scalar LDS. Crossbar per i drops 4096 -> 2560 cyc/SM.
    {
        float4* swbuf = (float4*)smem;                   // [2][2048] float4
        float*  sxt   = (float*)(smem + 2 * 32768);      // [2][16][36] floats

        const int t    = threadIdx.x;
        const int lane = t & 31;
        const int wid  = t >> 5;
        const int oq   = wid >> 3;       // o-quarter (0..3)
        const int bg   = wid & 7;        // b-group (4 b each)
        const int bx   = blockIdx.x;
        const int n    = (II - bx + nb - 1) / nb;
        const int qidx = oq * 32 + lane;            // float4 index within a c-row
        const int obase = oq * 128 + lane * 4;
        const int xc = t & 15, xb = (t >> 4) & 31;  // x-staging role (t < 512)

        ull sacc[4][2];
#pragma unroll
        for (int j = 0; j < 4; j++) { sacc[j][0] = 0ull; sacc[j][1] = 0ull; }

        // prefetch iteration 0
        {
            const float4* wsrc = (const float4*)(w + (size_t)bx * CC * OO);
            cpa16(&swbuf[t],        wsrc + t);
            cpa16(&swbuf[t + 1024], wsrc + t + 1024);
            if (t < 512)
                cpa4(&sxt[xc * XT_ROW + xb], x + (size_t)xb * II * CC + (size_t)bx * CC + xc);
        }
        CP_COMMIT();

        for (int it = 0; it < n; it++) {
            const int i = bx + it * nb;
            const bool hn = (it + 1) < n;
            if (hn) {
                const int i2 = i + nb;
                const int buf = (it + 1) & 1;
                const float4* wsrc = (const float4*)(w + (size_t)i2 * CC * OO);
                float4* wd = swbuf + buf * WBUF_F4;
                cpa16(&wd[t],        wsrc + t);
                cpa16(&wd[t + 1024], wsrc + t + 1024);
                if (t < 512)
                    cpa4(&sxt[buf * XT_BUF + xc * XT_ROW + xb],
                         x + (size_t)xb * II * CC + (size_t)i2 * CC + xc);
            }
            CP_COMMIT();
            if (hn) { CP_WAIT(1); } else { CP_WAIT(0); }
            __syncthreads();

            const float4* sw4 = swbuf + (it & 1) * WBUF_F4;
            const float*  sxp = sxt + (it & 1) * XT_BUF;

            ull acc[4][2];
#pragma unroll
            for (int j = 0; j < 4; j++) { acc[j][0] = 0ull; acc[j][1] = 0ull; }

#pragma unroll
            for (int c = 0; c < CC; c++) {
                const float4 wa = sw4[c * 128 + qidx];
                const float4 xq = *(const float4*)(sxp + c * XT_ROW + bg * 4);  // broadcast
                const ull wv0 = pack2(wa.x, wa.y);
                const ull wv1 = pack2(wa.z, wa.w);
                ull xx;
                xx = pack2(xq.x, xq.x); fma2(acc[0][0], xx, wv0); fma2(acc[0][1], xx, wv1);
                xx = pack2(xq.y, xq.y); fma2(acc[1][0], xx, wv0); fma2(acc[1][1], xx, wv1);
                xx = pack2(xq.z, xq.z); fma2(acc[2][0], xx, wv0); fma2(acc[2][1], xx, wv1);
                xx = pack2(xq.w, xq.w); fma2(acc[3][0], xx, wv0); fma2(acc[3][1], xx, wv1);
            }

            // store fp16 votes (256 B coalesced per warp per bb) + iter0 partials
#pragma unroll
            for (int bb = 0; bb < 4; bb++) {
                const int b = bg * 4 + bb;
                float l0, h0, l1, h1;
                unpack2(acc[bb][0], l0, h0);
                unpack2(acc[bb][1], l1, h1);
                __half2 hh[2] = { __floats2half2_rn(l0, h0), __floats2half2_rn(l1, h1) };
                *(uint2*)(g_votes + ((size_t)i * BB + b) * OO + obase) = *(uint2*)hh;
                add2(sacc[bb][0], acc[bb][0]);
                add2(sacc[bb][1], acc[bb][1]);
            }
            __syncthreads();   // compute done before this buffer is refilled
        }

        // deterministic per-block partial write (row = blockIdx.x)
#pragma unroll
        for (int bb = 0; bb < 4; bb++) {
            const int b = bg * 4 + bb;
            float l0, h0, l1, h1;
            unpack2(sacc[bb][0], l0, h0);
            unpack2(sacc[bb][1], l1, h1);
            *(float4*)(g_part + (size_t)bx * BO + b * OO + obase) = make_float4(l0, h0, l1, h1);
        }
    }

    grid_sync(nb);
    squash_phase(smem, nb, 1.0f / 32.0f, bias, g_actS, 0);  // actS = act0
    grid_sync(nb);
    route_phase<0>(nb);                                     // softmax(u(act0)); keep votes in L2
    grid_sync(nb);
    squash_phase(smem, nb, 1.0f, bias, g_actS, 1);          // actS = act0 + act1
    grid_sync(nb);
    route_phase<1>(nb);                                     // softmax(u(act0+act1)); streaming reads
    grid_sync(nb);
    squash_phase(smem, nb, 1.0f, bias, out, 0);             // final activation
}

// ---------------------------------------------------------------------------
extern "C" void kernel_launch(void* const* d_in, const int* in_sizes, int n_in,
                              void* d_out, int out_size) {
    const float* x    = (const float*)d_in[0];
    const float* w    = (const float*)d_in[1];
    const float* bias = (const float*)d_in[2];
    float* out = (float*)d_out;

    int dev = 0, sm = 148;
    cudaGetDevice(&dev);
    cudaDeviceGetAttribute(&sm, cudaDevAttrMultiProcessorCount, dev);
    int nb = sm < NBMAX ? sm : NBMAX;
    if (nb < 128) nb = 128;  // squash uses 128 blocks; all real targets have >=128 SMs

    cudaFuncSetAttribute(caps_kernel, cudaFuncAttributeMaxDynamicSharedMemorySize, SMEM_TOTAL);
    caps_kernel<<<nb, NT, SMEM_TOTAL>>>(x, w, bias, out, nb);
}